// round 7
// baseline (speedup 1.0000x reference)
#include <cuda_runtime.h>
#include <cuda_fp16.h>
#include <cstdint>
#include <math.h>

// ---------------- problem constants ----------------
#define B_  8
#define S_  2048
#define D_  1024
#define H_  1024
#define M_  (B_*S_)        // 16384
#define N2_ 2048           // interleaved (k,ph) output width
#define NC_ 16             // chunks per sequence (S_/BM)

// ---------------- scratch ----------------
__device__ __half g_Xh [(size_t)M_ * D_];     // fp16 K-permuted layer-0 input
__device__ __half g_X2 [(size_t)M_ * D_];     // fp16 K-permuted layer-1 input
__device__ __half g_Wc [(size_t)N2_ * D_];    // fp16 interleaved+permuted weights
// decoupled-lookback state: [layer][bx(8)][batch(8)][chunk(16)] -> 1024 per layer
__device__ int    g_status[2 * 1024];
__device__ float  g_aggA [2 * 1024 * 128];
__device__ float  g_aggB [2 * 1024 * 128];

// ---------------- helpers ----------------
__device__ __forceinline__ uint32_t h2_as_u32(__half2 h) {
    union { __half2 h; uint32_t u; } cvt; cvt.h = h; return cvt.u;
}
__device__ __forceinline__ uint32_t smem_u32(const void* p) {
    uint32_t a;
    asm("{ .reg .u64 t; cvta.to.shared.u64 t, %1; cvt.u32.u64 %0, t; }" : "=r"(a) : "l"(p));
    return a;
}
__device__ __forceinline__ void cpasync16(uint32_t dst, const void* src) {
    asm volatile("cp.async.cg.shared.global [%0], [%1], 16;" :: "r"(dst), "l"(src));
}
#define CP_COMMIT() asm volatile("cp.async.commit_group;" ::: "memory")

__device__ __forceinline__ void mma_fp16(float* c,
    uint32_t a0, uint32_t a1, uint32_t a2, uint32_t a3, uint32_t b0, uint32_t b1)
{
    asm volatile(
        "mma.sync.aligned.m16n8k16.row.col.f32.f16.f16.f32 "
        "{%0,%1,%2,%3}, {%4,%5,%6,%7}, {%8,%9}, {%0,%1,%2,%3};"
        : "+f"(c[0]), "+f"(c[1]), "+f"(c[2]), "+f"(c[3])
        : "r"(a0), "r"(a1), "r"(a2), "r"(a3), "r"(b0), "r"(b1));
}

__device__ __forceinline__ void gates2(float kv, float ph, float& a, float& b) {
    float z = __frcp_rn(1.f + __expf(-kv));   // sigmoid(kv)
    a = __frcp_rn(1.f + __expf(kv));          // sigmoid(-kv), overflow-safe
    float g = (ph >= 0.f) ? (ph + 0.5f) : __frcp_rn(1.f + __expf(-ph));
    b = z * g;
}

// K-permutation within each 16-group: pair slots (0,1),(8,9),(2,3),(10,11),
// (4,5),(12,13),(6,7),(14,15) — fragments {k=2t,2t+1, k=2t+8,2t+9} contiguous.
__device__ __forceinline__ void perm16(const float4 s0, const float4 s1,
                                       const float4 s2, const float4 s3,
                                       uint4& o0, uint4& o1)
{
    o0 = make_uint4(h2_as_u32(__floats2half2_rn(s0.x, s0.y)),
                    h2_as_u32(__floats2half2_rn(s2.x, s2.y)),
                    h2_as_u32(__floats2half2_rn(s0.z, s0.w)),
                    h2_as_u32(__floats2half2_rn(s2.z, s2.w)));
    o1 = make_uint4(h2_as_u32(__floats2half2_rn(s1.x, s1.y)),
                    h2_as_u32(__floats2half2_rn(s3.x, s3.y)),
                    h2_as_u32(__floats2half2_rn(s1.z, s1.w)),
                    h2_as_u32(__floats2half2_rn(s3.z, s3.w)));
}

// permuted column index (even h -> even slot; (2q,2q+1) pairs stay adjacent)
__device__ __forceinline__ int permcol16(int h) {
    int j = h & 15, q = j >> 1, r = j & 1;
    int slot = (q < 4) ? (2 * q) : (2 * (q - 4) + 1);
    return (h & ~15) | (slot * 2 + r);
}

// ---------------- fp32 -> fp16 + K-permute ----------------
__global__ __launch_bounds__(256) void round_kernel(
    const float4* __restrict__ src, uint4* __restrict__ dst, int n16)
{
    int i = blockIdx.x * 256 + threadIdx.x;
    if (i >= n16) return;
    uint4 o0, o1;
    perm16(src[4*i], src[4*i+1], src[4*i+2], src[4*i+3], o0, o1);
    dst[2*i] = o0; dst[2*i+1] = o1;
}

__global__ __launch_bounds__(256) void interleave_kernel(
    const float4* __restrict__ Wz, const float4* __restrict__ Wh, uint4* __restrict__ Wc)
{
    int i = blockIdx.x * 256 + threadIdx.x;      // over H_*D_/16 = 65536 groups
    int h = i >> 6, s = i & 63;
    uint4 z0, z1, h0, h1;
    perm16(Wz[4*i], Wz[4*i+1], Wz[4*i+2], Wz[4*i+3], z0, z1);
    perm16(Wh[4*i], Wh[4*i+1], Wh[4*i+2], Wh[4*i+3], h0, h1);
    uint4* rz = Wc + (size_t)(2*h)   * 128 + 2*s;
    uint4* rh = Wc + (size_t)(2*h+1) * 128 + 2*s;
    rz[0] = z0; rz[1] = z1;
    rh[0] = h0; rh[1] = h1;
}

__global__ void zero_status_kernel(int* st) {
    int i = blockIdx.x * 256 + threadIdx.x;
    if (i < 2 * 1024) st[i] = 0;
}

// ============================================================================
// Fused fp16 GEMM + gates + chunk scan (decoupled lookback) + output
// tile 128x256 (=> 128 h columns), warptile 64x64, BK=64, 3-stage cp.async
// ============================================================================
#define BM 128
#define BN 256
#define BK 64
#define ST 80
#define B_OFF (BM * ST)
#define STG_HALFS ((BM + BN) * ST)       // 30720
#define STG_BYTES (STG_HALFS * 2)        // 61440
#define GEMM_SMEM (3 * STG_BYTES)        // 184320
#define CST 132                          // epilogue smem column stride (floats)

__device__ __forceinline__ void load_stage(
    uint32_t sb, const __half* __restrict__ Ag, const __half* __restrict__ Bg,
    int k0, int tid)
{
    #pragma unroll
    for (int i = 0; i < 4; i++) {
        int s = tid + i * 256;
        int r = s >> 3, c = (s & 7) << 3;
        cpasync16(sb + (uint32_t)(r * ST + c) * 2, Ag + (size_t)r * D_ + k0 + c);
    }
    #pragma unroll
    for (int i = 0; i < 8; i++) {
        int s = tid + i * 256;
        int r = s >> 3, c = (s & 7) << 3;
        cpasync16(sb + (uint32_t)(B_OFF + r * ST + c) * 2, Bg + (size_t)r * D_ + k0 + c);
    }
    CP_COMMIT();
}

template<int MODE>   // 0: fp16 K-permuted out (next layer); 1: fp32 out
__global__ __launch_bounds__(256, 1) void gemm_fused_kernel(
    const __half* __restrict__ X, const __half* __restrict__ Wc,
    const float* __restrict__ bz, const float* __restrict__ bh,
    int* __restrict__ status, float* __restrict__ aggA, float* __restrict__ aggB,
    __half* __restrict__ outH, float* __restrict__ outF)
{
    extern __shared__ __align__(16) char smraw[];
    __half* sm = (__half*)smraw;
    const uint32_t sb = smem_u32(sm);
    const int tid = threadIdx.x;
    const int lane = tid & 31, wid = tid >> 5;
    const int g = lane >> 2, tg = lane & 3;
    const int wm = (wid >> 2) * 64;
    const int wn = (wid & 3) * 64;
    const int bm = blockIdx.y * BM;
    const int bn = blockIdx.x * BN;

    const __half* Ag = X  + (size_t)bm * D_;
    const __half* Bg = Wc + (size_t)bn * D_;

    float c[4][8][4];
    #pragma unroll
    for (int mt = 0; mt < 4; mt++)
        #pragma unroll
        for (int nt = 0; nt < 8; nt++)
            #pragma unroll
            for (int r = 0; r < 4; r++) c[mt][nt][r] = 0.f;

    load_stage(sb,             Ag, Bg, 0,  tid);
    load_stage(sb + STG_BYTES, Ag, Bg, BK, tid);

    const int NK = D_ / BK;   // 16
    for (int kt = 0; kt < NK; kt++) {
        asm volatile("cp.async.wait_group 1;" ::: "memory");
        __syncthreads();
        if (kt + 2 < NK)
            load_stage(sb + (uint32_t)((kt + 2) % 3) * STG_BYTES, Ag, Bg, (kt + 2) * BK, tid);
        else
            CP_COMMIT();

        const __half* As = sm + (kt % 3) * STG_HALFS;
        const __half* Bs = As + B_OFF;

        #pragma unroll
        for (int ks = 0; ks < 4; ks++) {
            const int kb = ks * 16 + 4 * tg;
            uint2 alo[4], ahi[4], bf[8];
            #pragma unroll
            for (int mt = 0; mt < 4; mt++) {
                const int m = wm + mt * 16 + g;
                alo[mt] = *(const uint2*)&As[m * ST + kb];
                ahi[mt] = *(const uint2*)&As[(m + 8) * ST + kb];
            }
            #pragma unroll
            for (int nt = 0; nt < 8; nt++) {
                const int n = wn + nt * 8 + g;
                bf[nt] = *(const uint2*)&Bs[n * ST + kb];
            }
            #pragma unroll
            for (int mt = 0; mt < 4; mt++)
                #pragma unroll
                for (int nt = 0; nt < 8; nt++)
                    mma_fp16(c[mt][nt], alo[mt].x, ahi[mt].x, alo[mt].y, ahi[mt].y,
                             bf[nt].x, bf[nt].y);
        }
    }

    // ---------- epilogue: gates -> smem tiles (t x h, stride CST) ----------
    __syncthreads();                      // all pipeline smem reads done
    float* sa  = (float*)smraw;           // a[t][h]
    float* sbv = sa + BM * CST;           // b[t][h] (later overwritten with h)

    const int hbase = bn >> 1;            // global h of column 0
    #pragma unroll
    for (int nt = 0; nt < 8; nt++) {
        const int hl = (wn >> 1) + nt * 4 + tg;     // 0..127
        const float bzv = bz[hbase + hl], bhv = bh[hbase + hl];
        #pragma unroll
        for (int mt = 0; mt < 4; mt++) {
            const int t0 = wm + mt * 16 + g;
            float a0, b0, a1, b1;
            gates2(c[mt][nt][0] + bzv, c[mt][nt][1] + bhv, a0, b0);
            gates2(c[mt][nt][2] + bzv, c[mt][nt][3] + bhv, a1, b1);
            sa [t0 * CST + hl]       = a0;
            sbv[t0 * CST + hl]       = b0;
            sa [(t0 + 8) * CST + hl] = a1;
            sbv[(t0 + 8) * CST + hl] = b1;
        }
    }
    __syncthreads();

    // ---------- chunk compose + publish aggregate ----------
    const int batch = blockIdx.y >> 4;
    const int chunk = blockIdx.y & 15;
    const int chain = blockIdx.x * B_ + batch;      // 0..63
    const int sidx  = chain * NC_ + chunk;          // 0..1023

    if (tid < 128) {
        const int hl = tid;
        float A = 1.f, Bv = 0.f;
        #pragma unroll 4
        for (int t = 0; t < BM; t++) {
            float a = sa[t * CST + hl], b = sbv[t * CST + hl];
            Bv = fmaf(a, Bv, b);
            A *= a;
        }
        aggA[(size_t)sidx * 128 + hl] = A;
        aggB[(size_t)sidx * 128 + hl] = Bv;
        __threadfence();
    }
    __syncthreads();
    if (tid == 0) atomicExch(&status[sidx], 1);

    // ---------- decoupled lookback + apply ----------
    if (tid < 128) {
        const int hl = tid;
        float Ar = 1.f, Br = 0.f;
        for (int p = chunk - 1; p >= 0; p--) {
            const int pidx = chain * NC_ + p;
            while (*(volatile int*)(status + pidx) == 0) __nanosleep(32);
            __threadfence();
            float Ap = aggA[(size_t)pidx * 128 + hl];
            float Bp = aggB[(size_t)pidx * 128 + hl];
            Br = fmaf(Ar, Bp, Br);
            Ar *= Ap;
        }
        float h = fmaf(Ar, 0.5f, Br);    // h_start (h0 = 0.5)
        #pragma unroll 4
        for (int t = 0; t < BM; t++) {
            float a = sa[t * CST + hl], b = sbv[t * CST + hl];
            h = fmaf(a, h, b);
            sbv[t * CST + hl] = h;       // overwrite b with h
        }
    }
    __syncthreads();

    // ---------- output write (coalesced, pairs) ----------
    if (MODE == 0) {
        for (int idx = tid; idx < BM * 64; idx += 256) {
            const int t = idx >> 6, pr = idx & 63;
            float2 v = *(const float2*)&sbv[t * CST + 2 * pr];
            __half2 hv = __floats2half2_rn(v.x, v.y);
            const int hp = permcol16(hbase + 2 * pr);
            *(__half2*)&outH[(size_t)(bm + t) * H_ + hp] = hv;
        }
    } else {
        for (int idx = tid; idx < BM * 64; idx += 256) {
            const int t = idx >> 6, pr = idx & 63;
            float2 v = *(const float2*)&sbv[t * CST + 2 * pr];
            *(float2*)&outF[(size_t)(bm + t) * H_ + hbase + 2 * pr] = v;
        }
    }
}

// ============================================================================
// launch
// ============================================================================
extern "C" void kernel_launch(void* const* d_in, const int* in_sizes, int n_in,
                              void* d_out, int out_size)
{
    const float* x  = (const float*)d_in[0];
    const float* Wz = (const float*)d_in[1];
    const float* bz = (const float*)d_in[2];
    const float* Wh = (const float*)d_in[3];
    const float* bh = (const float*)d_in[4];
    float* out = (float*)d_out;

    __half *Xh, *X2, *Wc;
    int* st;
    float *aA, *aB;
    cudaGetSymbolAddress((void**)&Xh, g_Xh);
    cudaGetSymbolAddress((void**)&X2, g_X2);
    cudaGetSymbolAddress((void**)&Wc, g_Wc);
    cudaGetSymbolAddress((void**)&st, g_status);
    cudaGetSymbolAddress((void**)&aA, g_aggA);
    cudaGetSymbolAddress((void**)&aB, g_aggB);

    cudaFuncSetAttribute(gemm_fused_kernel<0>,
                         cudaFuncAttributeMaxDynamicSharedMemorySize, GEMM_SMEM);
    cudaFuncSetAttribute(gemm_fused_kernel<1>,
                         cudaFuncAttributeMaxDynamicSharedMemorySize, GEMM_SMEM);

    const size_t HD = (size_t)H_ * D_;
    dim3 gemm_grid(N2_ / BN, M_ / BM);     // (8, 128)

    zero_status_kernel<<<8, 256>>>(st);
    round_kernel<<<(M_ * (size_t)D_ / 16 + 255) / 256, 256>>>(
        (const float4*)x, (uint4*)Xh, (int)((size_t)M_ * D_ / 16));

    // layer 0: Xh -> X2 (fp16 permuted)
    interleave_kernel<<<(HD / 16 + 255) / 256, 256>>>(
        (const float4*)Wz, (const float4*)Wh, (uint4*)Wc);
    gemm_fused_kernel<0><<<gemm_grid, 256, GEMM_SMEM>>>(
        Xh, Wc, bz, bh, st, aA, aB, X2, nullptr);

    // layer 1: X2 -> out (fp32)
    interleave_kernel<<<(HD / 16 + 255) / 256, 256>>>(
        (const float4*)(Wz + HD), (const float4*)(Wh + HD), (uint4*)Wc);
    gemm_fused_kernel<1><<<gemm_grid, 256, GEMM_SMEM>>>(
        X2, Wc, bz + H_, bh + H_, st + 1024, aA + (size_t)1024 * 128,
        aB + (size_t)1024 * 128, nullptr, out);
}

// round 8
// speedup vs baseline: 1.0080x; 1.0080x over previous
#include <cuda_runtime.h>
#include <cuda_fp16.h>
#include <cstdint>
#include <math.h>

// ---------------- problem constants ----------------
#define B_  8
#define S_  2048
#define D_  1024
#define H_  1024
#define M_  (B_*S_)        // 16384
#define N2_ 2048           // interleaved (k,ph) output width
#define NC_ 16             // chunks per sequence (S_/BM)

// ---------------- scratch ----------------
__device__ __half g_Xh [(size_t)M_ * D_];     // fp16 K-permuted layer-0 input
__device__ __half g_X2 [(size_t)M_ * D_];     // fp16 K-permuted layer-1 input
__device__ __half g_Wc [(size_t)N2_ * D_];    // fp16 interleaved+permuted weights
// decoupled-lookback state: [layer][bx(8)][batch(8)][chunk(16)] -> 1024 per layer
__device__ int    g_status[2 * 1024];
__device__ float  g_aggA [2 * 1024 * 128];
__device__ float  g_aggB [2 * 1024 * 128];

// ---------------- helpers ----------------
__device__ __forceinline__ uint32_t h2_as_u32(__half2 h) {
    union { __half2 h; uint32_t u; } cvt; cvt.h = h; return cvt.u;
}
__device__ __forceinline__ uint32_t smem_u32(const void* p) {
    uint32_t a;
    asm("{ .reg .u64 t; cvta.to.shared.u64 t, %1; cvt.u32.u64 %0, t; }" : "=r"(a) : "l"(p));
    return a;
}
__device__ __forceinline__ void cpasync16(uint32_t dst, const void* src) {
    asm volatile("cp.async.cg.shared.global [%0], [%1], 16;" :: "r"(dst), "l"(src));
}
#define CP_COMMIT() asm volatile("cp.async.commit_group;" ::: "memory")

__device__ __forceinline__ void mma_fp16(float* c,
    uint32_t a0, uint32_t a1, uint32_t a2, uint32_t a3, uint32_t b0, uint32_t b1)
{
    asm volatile(
        "mma.sync.aligned.m16n8k16.row.col.f32.f16.f16.f32 "
        "{%0,%1,%2,%3}, {%4,%5,%6,%7}, {%8,%9}, {%0,%1,%2,%3};"
        : "+f"(c[0]), "+f"(c[1]), "+f"(c[2]), "+f"(c[3])
        : "r"(a0), "r"(a1), "r"(a2), "r"(a3), "r"(b0), "r"(b1));
}

__device__ __forceinline__ void gates2(float kv, float ph, float& a, float& b) {
    float z = __frcp_rn(1.f + __expf(-kv));   // sigmoid(kv)
    a = __frcp_rn(1.f + __expf(kv));          // sigmoid(-kv), overflow-safe
    float g = (ph >= 0.f) ? (ph + 0.5f) : __frcp_rn(1.f + __expf(-ph));
    b = z * g;
}

// K-permutation within each 16-group (fragment pairs contiguous)
__device__ __forceinline__ void perm16(const float4 s0, const float4 s1,
                                       const float4 s2, const float4 s3,
                                       uint4& o0, uint4& o1)
{
    o0 = make_uint4(h2_as_u32(__floats2half2_rn(s0.x, s0.y)),
                    h2_as_u32(__floats2half2_rn(s2.x, s2.y)),
                    h2_as_u32(__floats2half2_rn(s0.z, s0.w)),
                    h2_as_u32(__floats2half2_rn(s2.z, s2.w)));
    o1 = make_uint4(h2_as_u32(__floats2half2_rn(s1.x, s1.y)),
                    h2_as_u32(__floats2half2_rn(s3.x, s3.y)),
                    h2_as_u32(__floats2half2_rn(s1.z, s1.w)),
                    h2_as_u32(__floats2half2_rn(s3.z, s3.w)));
}
__device__ __forceinline__ int permcol16(int h) {
    int j = h & 15, q = j >> 1, r = j & 1;
    int slot = (q < 4) ? (2 * q) : (2 * (q - 4) + 1);
    return (h & ~15) | (slot * 2 + r);
}

// ---------------- fp32 -> fp16 + K-permute ----------------
__global__ __launch_bounds__(256) void round_kernel(
    const float4* __restrict__ src, uint4* __restrict__ dst, int n16)
{
    int i = blockIdx.x * 256 + threadIdx.x;
    if (i >= n16) return;
    uint4 o0, o1;
    perm16(src[4*i], src[4*i+1], src[4*i+2], src[4*i+3], o0, o1);
    dst[2*i] = o0; dst[2*i+1] = o1;
}

__global__ __launch_bounds__(256) void interleave_kernel(
    const float4* __restrict__ Wz, const float4* __restrict__ Wh, uint4* __restrict__ Wc)
{
    int i = blockIdx.x * 256 + threadIdx.x;
    int h = i >> 6, s = i & 63;
    uint4 z0, z1, h0, h1;
    perm16(Wz[4*i], Wz[4*i+1], Wz[4*i+2], Wz[4*i+3], z0, z1);
    perm16(Wh[4*i], Wh[4*i+1], Wh[4*i+2], Wh[4*i+3], h0, h1);
    uint4* rz = Wc + (size_t)(2*h)   * 128 + 2*s;
    uint4* rh = Wc + (size_t)(2*h+1) * 128 + 2*s;
    rz[0] = z0; rz[1] = z1;
    rh[0] = h0; rh[1] = h1;
}

__global__ void zero_status_kernel(int* st) {
    int i = blockIdx.x * 256 + threadIdx.x;
    if (i < 2 * 1024) st[i] = 0;
}

// ============================================================================
// Fused fp16 GEMM + gates + chunk scan (decoupled lookback) + output
// ============================================================================
#define BM 128
#define BN 256
#define BK 64
#define ST 80
#define B_OFF (BM * ST)
#define STG_HALFS ((BM + BN) * ST)       // 30720
#define STG_BYTES (STG_HALFS * 2)        // 61440
#define GEMM_SMEM (3 * STG_BYTES)        // 184320
#define CST 132                          // epilogue smem column stride (floats)
#define AUX (2 * BM * CST)               // aux float offset (after sa+sbv)

__device__ __forceinline__ void load_stage(
    uint32_t sb, const __half* __restrict__ Ag, const __half* __restrict__ Bg,
    int k0, int tid)
{
    #pragma unroll
    for (int i = 0; i < 4; i++) {
        int s = tid + i * 256;
        int r = s >> 3, c = (s & 7) << 3;
        cpasync16(sb + (uint32_t)(r * ST + c) * 2, Ag + (size_t)r * D_ + k0 + c);
    }
    #pragma unroll
    for (int i = 0; i < 8; i++) {
        int s = tid + i * 256;
        int r = s >> 3, c = (s & 7) << 3;
        cpasync16(sb + (uint32_t)(B_OFF + r * ST + c) * 2, Bg + (size_t)r * D_ + k0 + c);
    }
    CP_COMMIT();
}

template<int MODE>   // 0: fp16 K-permuted out (next layer); 1: fp32 out
__global__ __launch_bounds__(256, 1) void gemm_fused_kernel(
    const __half* __restrict__ X, const __half* __restrict__ Wc,
    const float* __restrict__ bz, const float* __restrict__ bh,
    int* __restrict__ status, float* __restrict__ aggA, float* __restrict__ aggB,
    __half* __restrict__ outH, float* __restrict__ outF)
{
    extern __shared__ __align__(16) char smraw[];
    __half* sm = (__half*)smraw;
    const uint32_t sb = smem_u32(sm);
    const int tid = threadIdx.x;
    const int lane = tid & 31, wid = tid >> 5;
    const int g = lane >> 2, tg = lane & 3;
    const int wm = (wid >> 2) * 64;
    const int wn = (wid & 3) * 64;
    const int bm = blockIdx.y * BM;
    const int bn = blockIdx.x * BN;

    const __half* Ag = X  + (size_t)bm * D_;
    const __half* Bg = Wc + (size_t)bn * D_;

    float c[4][8][4];
    #pragma unroll
    for (int mt = 0; mt < 4; mt++)
        #pragma unroll
        for (int nt = 0; nt < 8; nt++)
            #pragma unroll
            for (int r = 0; r < 4; r++) c[mt][nt][r] = 0.f;

    load_stage(sb,             Ag, Bg, 0,  tid);
    load_stage(sb + STG_BYTES, Ag, Bg, BK, tid);

    const int NK = D_ / BK;   // 16
    for (int kt = 0; kt < NK; kt++) {
        asm volatile("cp.async.wait_group 1;" ::: "memory");
        __syncthreads();
        if (kt + 2 < NK)
            load_stage(sb + (uint32_t)((kt + 2) % 3) * STG_BYTES, Ag, Bg, (kt + 2) * BK, tid);
        else
            CP_COMMIT();

        const __half* As = sm + (kt % 3) * STG_HALFS;
        const __half* Bs = As + B_OFF;

        #pragma unroll
        for (int ks = 0; ks < 4; ks++) {
            const int kb = ks * 16 + 4 * tg;
            uint2 alo[4], ahi[4], bf[8];
            #pragma unroll
            for (int mt = 0; mt < 4; mt++) {
                const int m = wm + mt * 16 + g;
                alo[mt] = *(const uint2*)&As[m * ST + kb];
                ahi[mt] = *(const uint2*)&As[(m + 8) * ST + kb];
            }
            #pragma unroll
            for (int nt = 0; nt < 8; nt++) {
                const int n = wn + nt * 8 + g;
                bf[nt] = *(const uint2*)&Bs[n * ST + kb];
            }
            #pragma unroll
            for (int mt = 0; mt < 4; mt++)
                #pragma unroll
                for (int nt = 0; nt < 8; nt++)
                    mma_fp16(c[mt][nt], alo[mt].x, ahi[mt].x, alo[mt].y, ahi[mt].y,
                             bf[nt].x, bf[nt].y);
        }
    }

    // ---------- epilogue: gates -> smem tiles (t x h, stride CST) ----------
    __syncthreads();
    float* sa   = (float*)smraw;          // a[t][h]
    float* sbv  = sa + BM * CST;          // b[t][h] (later overwritten with h)
    float* segA = sa + AUX;               // [2][128] segment aggregates
    float* segB = segA + 256;
    float* shst = segB + 256;             // [128] chunk-start h

    const int hbase = bn >> 1;
    #pragma unroll
    for (int nt = 0; nt < 8; nt++) {
        const int hl = (wn >> 1) + nt * 4 + tg;
        const float bzv = bz[hbase + hl], bhv = bh[hbase + hl];
        #pragma unroll
        for (int mt = 0; mt < 4; mt++) {
            const int t0 = wm + mt * 16 + g;
            float a0, b0, a1, b1;
            gates2(c[mt][nt][0] + bzv, c[mt][nt][1] + bhv, a0, b0);
            gates2(c[mt][nt][2] + bzv, c[mt][nt][3] + bhv, a1, b1);
            sa [t0 * CST + hl]       = a0;
            sbv[t0 * CST + hl]       = b0;
            sa [(t0 + 8) * CST + hl] = a1;
            sbv[(t0 + 8) * CST + hl] = b1;
        }
    }
    __syncthreads();

    // ---------- parallel segment compose (2 threads per column) ----------
    const int batch = blockIdx.y >> 4;
    const int chunk = blockIdx.y & 15;
    const int chain = blockIdx.x * B_ + batch;
    const int sidx  = chain * NC_ + chunk;

    const int col  = tid & 127;
    const int half = tid >> 7;            // segment: t in [64*half, 64*half+64)
    const int tseg = half * 64;

    float A = 1.f, Bv = 0.f;
    #pragma unroll 4
    for (int t = 0; t < 64; t++) {
        float a = sa[(tseg + t) * CST + col], b = sbv[(tseg + t) * CST + col];
        Bv = fmaf(a, Bv, b);
        A *= a;
    }
    segA[half * 128 + col] = A;
    segB[half * 128 + col] = Bv;
    __syncthreads();

    // ---------- publish chunk aggregate (half 0 threads) ----------
    if (half == 0) {
        float A1 = segA[128 + col], B1 = segB[128 + col];
        aggA[(size_t)sidx * 128 + col] = A1 * A;             // A1*A0
        aggB[(size_t)sidx * 128 + col] = fmaf(A1, Bv, B1);   // A1*B0 + B1
        __threadfence();
    }
    __syncthreads();
    if (tid == 0) atomicExch(&status[sidx], 1);

    // ---------- decoupled lookback (half 0 threads) ----------
    if (half == 0) {
        float Ar = 1.f, Br = 0.f;
        for (int p = chunk - 1; p >= 0; p--) {
            const int pidx = chain * NC_ + p;
            while (*(volatile int*)(status + pidx) == 0) __nanosleep(32);
            __threadfence();
            float Ap = aggA[(size_t)pidx * 128 + col];
            float Bp = aggB[(size_t)pidx * 128 + col];
            Br = fmaf(Ar, Bp, Br);
            Ar *= Ap;
        }
        shst[col] = fmaf(Ar, 0.5f, Br);   // h at chunk start (h0 = 0.5)
    }
    __syncthreads();

    // ---------- parallel apply (both halves) ----------
    {
        float h = shst[col];
        if (half == 1)                    // h_mid = T_seg0(h_start)
            h = fmaf(segA[col], h, segB[col]);
        #pragma unroll 4
        for (int t = 0; t < 64; t++) {
            float a = sa[(tseg + t) * CST + col], b = sbv[(tseg + t) * CST + col];
            h = fmaf(a, h, b);
            sbv[(tseg + t) * CST + col] = h;
        }
    }
    __syncthreads();

    // ---------- output write (coalesced, pairs) ----------
    if (MODE == 0) {
        for (int idx = tid; idx < BM * 64; idx += 256) {
            const int t = idx >> 6, pr = idx & 63;
            float2 v = *(const float2*)&sbv[t * CST + 2 * pr];
            __half2 hv = __floats2half2_rn(v.x, v.y);
            const int hp = permcol16(hbase + 2 * pr);
            *(__half2*)&outH[(size_t)(bm + t) * H_ + hp] = hv;
        }
    } else {
        for (int idx = tid; idx < BM * 64; idx += 256) {
            const int t = idx >> 6, pr = idx & 63;
            float2 v = *(const float2*)&sbv[t * CST + 2 * pr];
            *(float2*)&outF[(size_t)(bm + t) * H_ + hbase + 2 * pr] = v;
        }
    }
}

// ============================================================================
// launch
// ============================================================================
extern "C" void kernel_launch(void* const* d_in, const int* in_sizes, int n_in,
                              void* d_out, int out_size)
{
    const float* x  = (const float*)d_in[0];
    const float* Wz = (const float*)d_in[1];
    const float* bz = (const float*)d_in[2];
    const float* Wh = (const float*)d_in[3];
    const float* bh = (const float*)d_in[4];
    float* out = (float*)d_out;

    __half *Xh, *X2, *Wc;
    int* st;
    float *aA, *aB;
    cudaGetSymbolAddress((void**)&Xh, g_Xh);
    cudaGetSymbolAddress((void**)&X2, g_X2);
    cudaGetSymbolAddress((void**)&Wc, g_Wc);
    cudaGetSymbolAddress((void**)&st, g_status);
    cudaGetSymbolAddress((void**)&aA, g_aggA);
    cudaGetSymbolAddress((void**)&aB, g_aggB);

    cudaFuncSetAttribute(gemm_fused_kernel<0>,
                         cudaFuncAttributeMaxDynamicSharedMemorySize, GEMM_SMEM);
    cudaFuncSetAttribute(gemm_fused_kernel<1>,
                         cudaFuncAttributeMaxDynamicSharedMemorySize, GEMM_SMEM);

    const size_t HD = (size_t)H_ * D_;
    dim3 gemm_grid(N2_ / BN, M_ / BM);     // (8, 128)

    zero_status_kernel<<<8, 256>>>(st);
    round_kernel<<<(M_ * (size_t)D_ / 16 + 255) / 256, 256>>>(
        (const float4*)x, (uint4*)Xh, (int)((size_t)M_ * D_ / 16));

    interleave_kernel<<<(HD / 16 + 255) / 256, 256>>>(
        (const float4*)Wz, (const float4*)Wh, (uint4*)Wc);
    gemm_fused_kernel<0><<<gemm_grid, 256, GEMM_SMEM>>>(
        Xh, Wc, bz, bh, st, aA, aB, X2, nullptr);

    interleave_kernel<<<(HD / 16 + 255) / 256, 256>>>(
        (const float4*)(Wz + HD), (const float4*)(Wh + HD), (uint4*)Wc);
    gemm_fused_kernel<1><<<gemm_grid, 256, GEMM_SMEM>>>(
        X2, Wc, bz + H_, bh + H_, st + 1024, aA + (size_t)1024 * 128,
        aB + (size_t)1024 * 128, nullptr, out);
}

// round 9
// speedup vs baseline: 1.0648x; 1.0563x over previous
#include <cuda_runtime.h>
#include <cuda_fp16.h>
#include <cstdint>
#include <math.h>

// ---------------- problem constants ----------------
#define B_  8
#define S_  2048
#define D_  1024
#define H_  1024
#define M_  (B_*S_)        // 16384
#define N2_ 2048           // interleaved (k,ph) output width
#define NC_ 16             // chunks per sequence (S_/BM)
#define NCHAIN_ 128        // chains per layer: 16 h-tiles x 8 batches

// ---------------- scratch ----------------
__device__ __half g_Xh [(size_t)M_ * D_];     // fp16 K-permuted layer-0 input
__device__ __half g_X2 [(size_t)M_ * D_];     // fp16 K-permuted layer-1 input
__device__ __half g_Wc [(size_t)N2_ * D_];    // fp16 interleaved+permuted weights
// decoupled-lookback state: [layer][hx(16)][batch(8)][chunk(16)]
__device__ int    g_status[2 * NCHAIN_ * NC_];
__device__ float  g_aggA [2 * NCHAIN_ * NC_ * 64];
__device__ float  g_aggB [2 * NCHAIN_ * NC_ * 64];

// ---------------- helpers ----------------
__device__ __forceinline__ uint32_t h2_as_u32(__half2 h) {
    union { __half2 h; uint32_t u; } cvt; cvt.h = h; return cvt.u;
}
__device__ __forceinline__ uint32_t smem_u32(const void* p) {
    uint32_t a;
    asm("{ .reg .u64 t; cvta.to.shared.u64 t, %1; cvt.u32.u64 %0, t; }" : "=r"(a) : "l"(p));
    return a;
}
__device__ __forceinline__ void cpasync16(uint32_t dst, const void* src) {
    asm volatile("cp.async.cg.shared.global [%0], [%1], 16;" :: "r"(dst), "l"(src));
}
#define CP_COMMIT() asm volatile("cp.async.commit_group;" ::: "memory")

__device__ __forceinline__ void mma_fp16(float* c,
    uint32_t a0, uint32_t a1, uint32_t a2, uint32_t a3, uint32_t b0, uint32_t b1)
{
    asm volatile(
        "mma.sync.aligned.m16n8k16.row.col.f32.f16.f16.f32 "
        "{%0,%1,%2,%3}, {%4,%5,%6,%7}, {%8,%9}, {%0,%1,%2,%3};"
        : "+f"(c[0]), "+f"(c[1]), "+f"(c[2]), "+f"(c[3])
        : "r"(a0), "r"(a1), "r"(a2), "r"(a3), "r"(b0), "r"(b1));
}

__device__ __forceinline__ void gates2(float kv, float ph, float& a, float& b) {
    float z = __frcp_rn(1.f + __expf(-kv));   // sigmoid(kv)
    a = __frcp_rn(1.f + __expf(kv));          // sigmoid(-kv), overflow-safe
    float g = (ph >= 0.f) ? (ph + 0.5f) : __frcp_rn(1.f + __expf(-ph));
    b = z * g;
}

// K-permutation within each 16-group (fragment pairs contiguous)
__device__ __forceinline__ void perm16(const float4 s0, const float4 s1,
                                       const float4 s2, const float4 s3,
                                       uint4& o0, uint4& o1)
{
    o0 = make_uint4(h2_as_u32(__floats2half2_rn(s0.x, s0.y)),
                    h2_as_u32(__floats2half2_rn(s2.x, s2.y)),
                    h2_as_u32(__floats2half2_rn(s0.z, s0.w)),
                    h2_as_u32(__floats2half2_rn(s2.z, s2.w)));
    o1 = make_uint4(h2_as_u32(__floats2half2_rn(s1.x, s1.y)),
                    h2_as_u32(__floats2half2_rn(s3.x, s3.y)),
                    h2_as_u32(__floats2half2_rn(s1.z, s1.w)),
                    h2_as_u32(__floats2half2_rn(s3.z, s3.w)));
}
__device__ __forceinline__ int permcol16(int h) {
    int j = h & 15, q = j >> 1, r = j & 1;
    int slot = (q < 4) ? (2 * q) : (2 * (q - 4) + 1);
    return (h & ~15) | (slot * 2 + r);
}

// ---------------- fp32 -> fp16 + K-permute ----------------
__global__ __launch_bounds__(256) void round_kernel(
    const float4* __restrict__ src, uint4* __restrict__ dst, int n16)
{
    int i = blockIdx.x * 256 + threadIdx.x;
    if (i >= n16) return;
    uint4 o0, o1;
    perm16(src[4*i], src[4*i+1], src[4*i+2], src[4*i+3], o0, o1);
    dst[2*i] = o0; dst[2*i+1] = o1;
}

__global__ __launch_bounds__(256) void interleave_kernel(
    const float4* __restrict__ Wz, const float4* __restrict__ Wh, uint4* __restrict__ Wc)
{
    int i = blockIdx.x * 256 + threadIdx.x;
    int h = i >> 6, s = i & 63;
    uint4 z0, z1, h0, h1;
    perm16(Wz[4*i], Wz[4*i+1], Wz[4*i+2], Wz[4*i+3], z0, z1);
    perm16(Wh[4*i], Wh[4*i+1], Wh[4*i+2], Wh[4*i+3], h0, h1);
    uint4* rz = Wc + (size_t)(2*h)   * 128 + 2*s;
    uint4* rh = Wc + (size_t)(2*h+1) * 128 + 2*s;
    rz[0] = z0; rz[1] = z1;
    rh[0] = h0; rh[1] = h1;
}

__global__ void zero_status_kernel(int* st) {
    int i = blockIdx.x * 256 + threadIdx.x;
    if (i < 2 * NCHAIN_ * NC_) st[i] = 0;
}

// ============================================================================
// Fused fp16 GEMM + gates + chunk scan (decoupled lookback) + output
// tile 128x128 (64 h columns), warptile 64x32, BK=64, 3-stage, 2 blocks/SM
// ============================================================================
#define BM 128
#define BN 128
#define BK 64
#define ST 72                            // halfs per smem row (64 + 8 pad)
#define B_OFF (BM * ST)
#define STG_HALFS ((BM + BN) * ST)       // 18432
#define STG_BYTES (STG_HALFS * 2)        // 36864
#define GEMM_SMEM (3 * STG_BYTES)        // 110592
#define CST 68                           // epilogue smem column stride (floats)

__device__ __forceinline__ void load_stage(
    uint32_t sb, const __half* __restrict__ Ag, const __half* __restrict__ Bg,
    int k0, int tid)
{
    #pragma unroll
    for (int i = 0; i < 4; i++) {        // A: 128 rows x 8 x 16B
        int s = tid + i * 256;
        int r = s >> 3, c = (s & 7) << 3;
        cpasync16(sb + (uint32_t)(r * ST + c) * 2, Ag + (size_t)r * D_ + k0 + c);
    }
    #pragma unroll
    for (int i = 0; i < 4; i++) {        // B: 128 rows x 8 x 16B
        int s = tid + i * 256;
        int r = s >> 3, c = (s & 7) << 3;
        cpasync16(sb + (uint32_t)(B_OFF + r * ST + c) * 2, Bg + (size_t)r * D_ + k0 + c);
    }
    CP_COMMIT();
}

template<int MODE>   // 0: fp16 K-permuted out (next layer); 1: fp32 out
__global__ __launch_bounds__(256, 2) void gemm_fused_kernel(
    const __half* __restrict__ X, const __half* __restrict__ Wc,
    const float* __restrict__ bz, const float* __restrict__ bh,
    int* __restrict__ status, float* __restrict__ aggA, float* __restrict__ aggB,
    __half* __restrict__ outH, float* __restrict__ outF)
{
    extern __shared__ __align__(16) char smraw[];
    __half* sm = (__half*)smraw;
    const uint32_t sb = smem_u32(sm);
    const int tid = threadIdx.x;
    const int lane = tid & 31, wid = tid >> 5;
    const int g = lane >> 2, tg = lane & 3;
    const int wm = (wid >> 2) * 64;      // 0 / 64
    const int wn = (wid & 3) * 32;       // 0 / 32 / 64 / 96
    const int bm = blockIdx.y * BM;
    const int bn = blockIdx.x * BN;

    const __half* Ag = X  + (size_t)bm * D_;
    const __half* Bg = Wc + (size_t)bn * D_;

    float c[4][4][4];
    #pragma unroll
    for (int mt = 0; mt < 4; mt++)
        #pragma unroll
        for (int nt = 0; nt < 4; nt++)
            #pragma unroll
            for (int r = 0; r < 4; r++) c[mt][nt][r] = 0.f;

    load_stage(sb,             Ag, Bg, 0,  tid);
    load_stage(sb + STG_BYTES, Ag, Bg, BK, tid);

    const int NK = D_ / BK;   // 16
    for (int kt = 0; kt < NK; kt++) {
        asm volatile("cp.async.wait_group 1;" ::: "memory");
        __syncthreads();
        if (kt + 2 < NK)
            load_stage(sb + (uint32_t)((kt + 2) % 3) * STG_BYTES, Ag, Bg, (kt + 2) * BK, tid);
        else
            CP_COMMIT();

        const __half* As = sm + (kt % 3) * STG_HALFS;
        const __half* Bs = As + B_OFF;

        #pragma unroll
        for (int ks = 0; ks < 4; ks++) {
            const int kb = ks * 16 + 4 * tg;
            uint2 alo[4], ahi[4], bf[4];
            #pragma unroll
            for (int mt = 0; mt < 4; mt++) {
                const int m = wm + mt * 16 + g;
                alo[mt] = *(const uint2*)&As[m * ST + kb];
                ahi[mt] = *(const uint2*)&As[(m + 8) * ST + kb];
            }
            #pragma unroll
            for (int nt = 0; nt < 4; nt++) {
                const int n = wn + nt * 8 + g;
                bf[nt] = *(const uint2*)&Bs[n * ST + kb];
            }
            #pragma unroll
            for (int mt = 0; mt < 4; mt++)
                #pragma unroll
                for (int nt = 0; nt < 4; nt++)
                    mma_fp16(c[mt][nt], alo[mt].x, ahi[mt].x, alo[mt].y, ahi[mt].y,
                             bf[nt].x, bf[nt].y);
        }
    }

    // ---------- epilogue: gates -> smem tiles (t x h, stride CST) ----------
    __syncthreads();
    float* sa   = (float*)smraw;          // a[t][h]   128 x CST
    float* sbv  = sa + BM * CST;          // b[t][h] (later overwritten with h)
    float* segA = sbv + BM * CST;         // [4][64] segment aggregates
    float* segB = segA + 256;
    float* shst = segB + 256;             // [64] chunk-start h

    const int hbase = bn >> 1;            // global h of column 0 (64 cols/block)
    #pragma unroll
    for (int nt = 0; nt < 4; nt++) {
        const int hl = (wn >> 1) + nt * 4 + tg;     // 0..63
        const float bzv = bz[hbase + hl], bhv = bh[hbase + hl];
        #pragma unroll
        for (int mt = 0; mt < 4; mt++) {
            const int t0 = wm + mt * 16 + g;
            float a0, b0, a1, b1;
            gates2(c[mt][nt][0] + bzv, c[mt][nt][1] + bhv, a0, b0);
            gates2(c[mt][nt][2] + bzv, c[mt][nt][3] + bhv, a1, b1);
            sa [t0 * CST + hl]       = a0;
            sbv[t0 * CST + hl]       = b0;
            sa [(t0 + 8) * CST + hl] = a1;
            sbv[(t0 + 8) * CST + hl] = b1;
        }
    }
    __syncthreads();

    // ---------- segment compose: 4 threads/column, 32 steps each ----------
    const int batch = blockIdx.y >> 4;
    const int chunk = blockIdx.y & 15;
    const int chain = blockIdx.x * B_ + batch;      // 0..127
    const int sidx  = chain * NC_ + chunk;

    const int col = tid & 63;
    const int seg = tid >> 6;             // 0..3; rows [32*seg, 32*seg+32)
    const int tseg = seg * 32;

    {
        float A = 1.f, Bv = 0.f;
        #pragma unroll 4
        for (int t = 0; t < 32; t++) {
            float a = sa[(tseg + t) * CST + col], b = sbv[(tseg + t) * CST + col];
            Bv = fmaf(a, Bv, b);
            A *= a;
        }
        segA[seg * 64 + col] = A;
        segB[seg * 64 + col] = Bv;
    }
    __syncthreads();

    // ---------- combine + publish chunk aggregate (seg 0 threads) ----------
    if (seg == 0) {
        float Ac = segA[col], Bc = segB[col];
        #pragma unroll
        for (int s = 1; s < 4; s++) {
            float As_ = segA[s * 64 + col], Bs_ = segB[s * 64 + col];
            Bc = fmaf(As_, Bc, Bs_);
            Ac *= As_;
        }
        aggA[(size_t)sidx * 64 + col] = Ac;
        aggB[(size_t)sidx * 64 + col] = Bc;
        __threadfence();
    }
    __syncthreads();
    if (tid == 0) atomicExch(&status[sidx], 1);

    // ---------- decoupled lookback (seg 0 threads) ----------
    if (seg == 0) {
        float Ar = 1.f, Br = 0.f;
        for (int p = chunk - 1; p >= 0; p--) {
            const int pidx = chain * NC_ + p;
            while (*(volatile int*)(status + pidx) == 0) __nanosleep(32);
            __threadfence();
            float Ap = aggA[(size_t)pidx * 64 + col];
            float Bp = aggB[(size_t)pidx * 64 + col];
            Br = fmaf(Ar, Bp, Br);
            Ar *= Ap;
        }
        shst[col] = fmaf(Ar, 0.5f, Br);   // h at chunk start (h0 = 0.5)
    }
    __syncthreads();

    // ---------- parallel apply (all 4 segments) ----------
    {
        float h = shst[col];
        #pragma unroll
        for (int s = 0; s < 4; s++)       // prefix through earlier segments
            if (s < seg) h = fmaf(segA[s * 64 + col], h, segB[s * 64 + col]);
        #pragma unroll 4
        for (int t = 0; t < 32; t++) {
            float a = sa[(tseg + t) * CST + col], b = sbv[(tseg + t) * CST + col];
            h = fmaf(a, h, b);
            sbv[(tseg + t) * CST + col] = h;
        }
    }
    __syncthreads();

    // ---------- output write (coalesced, pairs) ----------
    if (MODE == 0) {
        for (int idx = tid; idx < BM * 32; idx += 256) {
            const int t = idx >> 5, pr = idx & 31;
            float2 v = *(const float2*)&sbv[t * CST + 2 * pr];
            __half2 hv = __floats2half2_rn(v.x, v.y);
            const int hp = permcol16(hbase + 2 * pr);
            *(__half2*)&outH[(size_t)(bm + t) * H_ + hp] = hv;
        }
    } else {
        for (int idx = tid; idx < BM * 32; idx += 256) {
            const int t = idx >> 5, pr = idx & 31;
            float2 v = *(const float2*)&sbv[t * CST + 2 * pr];
            *(float2*)&outF[(size_t)(bm + t) * H_ + hbase + 2 * pr] = v;
        }
    }
}

// ============================================================================
// launch
// ============================================================================
extern "C" void kernel_launch(void* const* d_in, const int* in_sizes, int n_in,
                              void* d_out, int out_size)
{
    const float* x  = (const float*)d_in[0];
    const float* Wz = (const float*)d_in[1];
    const float* bz = (const float*)d_in[2];
    const float* Wh = (const float*)d_in[3];
    const float* bh = (const float*)d_in[4];
    float* out = (float*)d_out;

    __half *Xh, *X2, *Wc;
    int* st;
    float *aA, *aB;
    cudaGetSymbolAddress((void**)&Xh, g_Xh);
    cudaGetSymbolAddress((void**)&X2, g_X2);
    cudaGetSymbolAddress((void**)&Wc, g_Wc);
    cudaGetSymbolAddress((void**)&st, g_status);
    cudaGetSymbolAddress((void**)&aA, g_aggA);
    cudaGetSymbolAddress((void**)&aB, g_aggB);

    cudaFuncSetAttribute(gemm_fused_kernel<0>,
                         cudaFuncAttributeMaxDynamicSharedMemorySize, GEMM_SMEM);
    cudaFuncSetAttribute(gemm_fused_kernel<1>,
                         cudaFuncAttributeMaxDynamicSharedMemorySize, GEMM_SMEM);

    const size_t HD = (size_t)H_ * D_;
    const size_t LSTRIDE = (size_t)NCHAIN_ * NC_;   // per-layer status stride
    dim3 gemm_grid(N2_ / BN, M_ / BM);     // (16, 128)

    zero_status_kernel<<<16, 256>>>(st);
    round_kernel<<<(M_ * (size_t)D_ / 16 + 255) / 256, 256>>>(
        (const float4*)x, (uint4*)Xh, (int)((size_t)M_ * D_ / 16));

    interleave_kernel<<<(HD / 16 + 255) / 256, 256>>>(
        (const float4*)Wz, (const float4*)Wh, (uint4*)Wc);
    gemm_fused_kernel<0><<<gemm_grid, 256, GEMM_SMEM>>>(
        Xh, Wc, bz, bh, st, aA, aB, X2, nullptr);

    interleave_kernel<<<(HD / 16 + 255) / 256, 256>>>(
        (const float4*)(Wz + HD), (const float4*)(Wh + HD), (uint4*)Wc);
    gemm_fused_kernel<1><<<gemm_grid, 256, GEMM_SMEM>>>(
        X2, Wc, bz + H_, bh + H_, st + LSTRIDE, aA + LSTRIDE * 64,
        aB + LSTRIDE * 64, nullptr, out);
}

// round 10
// speedup vs baseline: 1.2159x; 1.1420x over previous
#include <cuda_runtime.h>
#include <cuda_fp16.h>
#include <cstdint>
#include <math.h>

// ---------------- problem constants ----------------
#define B_  8
#define S_  2048
#define D_  1024
#define H_  1024
#define M_  (B_*S_)        // 16384
#define N2_ 2048           // interleaved (k,ph) output width
#define NC_ 16             // chunks per sequence (S_/BM)
#define NCHAIN_ 128        // chains per layer: 16 h-tiles x 8 batches

// ---------------- scratch ----------------
__device__ __half g_Xh [(size_t)M_ * D_];     // fp16 K-permuted layer-0 input
__device__ __half g_X2 [(size_t)M_ * D_];     // fp16 K-permuted layer-1 input
__device__ __half g_Wc [(size_t)N2_ * D_];    // fp16 interleaved+permuted weights
// decoupled-lookback state: [layer][hx(16)][batch(8)][chunk(16)]
__device__ int    g_status[2 * NCHAIN_ * NC_];
__device__ float  g_aggA [2 * NCHAIN_ * NC_ * 64];
__device__ float  g_aggB [2 * NCHAIN_ * NC_ * 64];

// ---------------- helpers ----------------
__device__ __forceinline__ uint32_t h2_as_u32(__half2 h) {
    union { __half2 h; uint32_t u; } cvt; cvt.h = h; return cvt.u;
}
__device__ __forceinline__ uint32_t smem_u32(const void* p) {
    uint32_t a;
    asm("{ .reg .u64 t; cvta.to.shared.u64 t, %1; cvt.u32.u64 %0, t; }" : "=r"(a) : "l"(p));
    return a;
}
__device__ __forceinline__ void cpasync16(uint32_t dst, const void* src) {
    asm volatile("cp.async.cg.shared.global [%0], [%1], 16;" :: "r"(dst), "l"(src));
}
#define CP_COMMIT() asm volatile("cp.async.commit_group;" ::: "memory")

__device__ __forceinline__ void mma_fp16(float* c,
    uint32_t a0, uint32_t a1, uint32_t a2, uint32_t a3, uint32_t b0, uint32_t b1)
{
    asm volatile(
        "mma.sync.aligned.m16n8k16.row.col.f32.f16.f16.f32 "
        "{%0,%1,%2,%3}, {%4,%5,%6,%7}, {%8,%9}, {%0,%1,%2,%3};"
        : "+f"(c[0]), "+f"(c[1]), "+f"(c[2]), "+f"(c[3])
        : "r"(a0), "r"(a1), "r"(a2), "r"(a3), "r"(b0), "r"(b1));
}

__device__ __forceinline__ void gates2(float kv, float ph, float& a, float& b) {
    float z = __frcp_rn(1.f + __expf(-kv));   // sigmoid(kv)
    a = __frcp_rn(1.f + __expf(kv));          // sigmoid(-kv), overflow-safe
    float g = (ph >= 0.f) ? (ph + 0.5f) : __frcp_rn(1.f + __expf(-ph));
    b = z * g;
}

// K-permutation within each 16-group (fragment pairs contiguous)
__device__ __forceinline__ void perm16(const float4 s0, const float4 s1,
                                       const float4 s2, const float4 s3,
                                       uint4& o0, uint4& o1)
{
    o0 = make_uint4(h2_as_u32(__floats2half2_rn(s0.x, s0.y)),
                    h2_as_u32(__floats2half2_rn(s2.x, s2.y)),
                    h2_as_u32(__floats2half2_rn(s0.z, s0.w)),
                    h2_as_u32(__floats2half2_rn(s2.z, s2.w)));
    o1 = make_uint4(h2_as_u32(__floats2half2_rn(s1.x, s1.y)),
                    h2_as_u32(__floats2half2_rn(s3.x, s3.y)),
                    h2_as_u32(__floats2half2_rn(s1.z, s1.w)),
                    h2_as_u32(__floats2half2_rn(s3.z, s3.w)));
}
__device__ __forceinline__ int permcol16(int h) {
    int j = h & 15, q = j >> 1, r = j & 1;
    int slot = (q < 4) ? (2 * q) : (2 * (q - 4) + 1);
    return (h & ~15) | (slot * 2 + r);
}

// ---------------- fp32 -> fp16 + K-permute ----------------
__global__ __launch_bounds__(256) void round_kernel(
    const float4* __restrict__ src, uint4* __restrict__ dst, int n16)
{
    int i = blockIdx.x * 256 + threadIdx.x;
    if (i >= n16) return;
    uint4 o0, o1;
    perm16(src[4*i], src[4*i+1], src[4*i+2], src[4*i+3], o0, o1);
    dst[2*i] = o0; dst[2*i+1] = o1;
}

__global__ __launch_bounds__(256) void interleave_kernel(
    const float4* __restrict__ Wz, const float4* __restrict__ Wh, uint4* __restrict__ Wc)
{
    int i = blockIdx.x * 256 + threadIdx.x;
    int h = i >> 6, s = i & 63;
    uint4 z0, z1, h0, h1;
    perm16(Wz[4*i], Wz[4*i+1], Wz[4*i+2], Wz[4*i+3], z0, z1);
    perm16(Wh[4*i], Wh[4*i+1], Wh[4*i+2], Wh[4*i+3], h0, h1);
    uint4* rz = Wc + (size_t)(2*h)   * 128 + 2*s;
    uint4* rh = Wc + (size_t)(2*h+1) * 128 + 2*s;
    rz[0] = z0; rz[1] = z1;
    rh[0] = h0; rh[1] = h1;
}

__global__ void zero_status_kernel(int* st) {
    int i = blockIdx.x * 256 + threadIdx.x;
    if (i < 2 * NCHAIN_ * NC_) st[i] = 0;
}

// ============================================================================
// Fused fp16 GEMM + gates + chunk scan (decoupled lookback) + output
// tile 128x128 (64 h cols), warptile 64x32, BK=32, 4-stage, 2 blocks/SM
// ST=48 halfs: 12 words8 mod 16 = 12 -> phase banks {0-3,12-15,8-11,4-7} distinct
// ============================================================================
#define BM 128
#define BN 128
#define BK 32
#define ST 48                            // halfs per smem row (32 + 16 pad)
#define B_OFF (BM * ST)
#define STG_HALFS ((BM + BN) * ST)       // 12288
#define STG_BYTES (STG_HALFS * 2)        // 24576
#define NSTAGE 4
#define GEMM_SMEM (NSTAGE * STG_BYTES)   // 98304
#define CST 68                           // epilogue smem column stride (floats)

__device__ __forceinline__ void load_stage(
    uint32_t sb, const __half* __restrict__ Ag, const __half* __restrict__ Bg,
    int k0, int tid)
{
    #pragma unroll
    for (int i = 0; i < 2; i++) {        // A: 128 rows x 4 x 16B
        int s = tid + i * 256;
        int r = s >> 2, c = (s & 3) << 3;
        cpasync16(sb + (uint32_t)(r * ST + c) * 2, Ag + (size_t)r * D_ + k0 + c);
    }
    #pragma unroll
    for (int i = 0; i < 2; i++) {        // B: 128 rows x 4 x 16B
        int s = tid + i * 256;
        int r = s >> 2, c = (s & 3) << 3;
        cpasync16(sb + (uint32_t)(B_OFF + r * ST + c) * 2, Bg + (size_t)r * D_ + k0 + c);
    }
    CP_COMMIT();
}

template<int MODE>   // 0: fp16 K-permuted out (next layer); 1: fp32 out
__global__ __launch_bounds__(256, 2) void gemm_fused_kernel(
    const __half* __restrict__ X, const __half* __restrict__ Wc,
    const float* __restrict__ bz, const float* __restrict__ bh,
    int* __restrict__ status, float* __restrict__ aggA, float* __restrict__ aggB,
    __half* __restrict__ outH, float* __restrict__ outF)
{
    extern __shared__ __align__(16) char smraw[];
    __half* sm = (__half*)smraw;
    const uint32_t sb = smem_u32(sm);
    const int tid = threadIdx.x;
    const int lane = tid & 31, wid = tid >> 5;
    const int g = lane >> 2, tg = lane & 3;
    const int wm = (wid >> 2) * 64;      // 0 / 64
    const int wn = (wid & 3) * 32;       // 0 / 32 / 64 / 96
    const int bm = blockIdx.y * BM;
    const int bn = blockIdx.x * BN;

    const __half* Ag = X  + (size_t)bm * D_;
    const __half* Bg = Wc + (size_t)bn * D_;

    float c[4][4][4];
    #pragma unroll
    for (int mt = 0; mt < 4; mt++)
        #pragma unroll
        for (int nt = 0; nt < 4; nt++)
            #pragma unroll
            for (int r = 0; r < 4; r++) c[mt][nt][r] = 0.f;

    load_stage(sb,                 Ag, Bg, 0,      tid);
    load_stage(sb + STG_BYTES,     Ag, Bg, BK,     tid);
    load_stage(sb + 2 * STG_BYTES, Ag, Bg, 2 * BK, tid);

    const int NK = D_ / BK;   // 32
    for (int kt = 0; kt < NK; kt++) {
        asm volatile("cp.async.wait_group 2;" ::: "memory");
        __syncthreads();
        if (kt + 3 < NK)
            load_stage(sb + (uint32_t)((kt + 3) % NSTAGE) * STG_BYTES,
                       Ag, Bg, (kt + 3) * BK, tid);
        else
            CP_COMMIT();

        const __half* As = sm + (kt % NSTAGE) * STG_HALFS;
        const __half* Bs = As + B_OFF;

        #pragma unroll
        for (int ks = 0; ks < 2; ks++) {              // 2 k16-groups per BK=32
            const int kb = ks * 16 + 4 * tg;
            uint2 alo[4], ahi[4], bf[4];
            #pragma unroll
            for (int mt = 0; mt < 4; mt++) {
                const int m = wm + mt * 16 + g;
                alo[mt] = *(const uint2*)&As[m * ST + kb];
                ahi[mt] = *(const uint2*)&As[(m + 8) * ST + kb];
            }
            #pragma unroll
            for (int nt = 0; nt < 4; nt++) {
                const int n = wn + nt * 8 + g;
                bf[nt] = *(const uint2*)&Bs[n * ST + kb];
            }
            #pragma unroll
            for (int mt = 0; mt < 4; mt++)
                #pragma unroll
                for (int nt = 0; nt < 4; nt++)
                    mma_fp16(c[mt][nt], alo[mt].x, ahi[mt].x, alo[mt].y, ahi[mt].y,
                             bf[nt].x, bf[nt].y);
        }
    }

    // ---------- epilogue: gates -> smem tiles (t x h, stride CST) ----------
    __syncthreads();
    float* sa   = (float*)smraw;          // a[t][h]   128 x CST
    float* sbv  = sa + BM * CST;          // b[t][h] (later overwritten with h)
    float* segA = sbv + BM * CST;         // [4][64] segment aggregates
    float* segB = segA + 256;
    float* shst = segB + 256;             // [64] chunk-start h

    const int hbase = bn >> 1;            // global h of column 0 (64 cols/block)
    #pragma unroll
    for (int nt = 0; nt < 4; nt++) {
        const int hl = (wn >> 1) + nt * 4 + tg;     // 0..63
        const float bzv = bz[hbase + hl], bhv = bh[hbase + hl];
        #pragma unroll
        for (int mt = 0; mt < 4; mt++) {
            const int t0 = wm + mt * 16 + g;
            float a0, b0, a1, b1;
            gates2(c[mt][nt][0] + bzv, c[mt][nt][1] + bhv, a0, b0);
            gates2(c[mt][nt][2] + bzv, c[mt][nt][3] + bhv, a1, b1);
            sa [t0 * CST + hl]       = a0;
            sbv[t0 * CST + hl]       = b0;
            sa [(t0 + 8) * CST + hl] = a1;
            sbv[(t0 + 8) * CST + hl] = b1;
        }
    }
    __syncthreads();

    // ---------- segment compose: 4 threads/column, 32 steps each ----------
    const int batch = blockIdx.y >> 4;
    const int chunk = blockIdx.y & 15;
    const int chain = blockIdx.x * B_ + batch;      // 0..127
    const int sidx  = chain * NC_ + chunk;

    const int col = tid & 63;
    const int seg = tid >> 6;             // 0..3; rows [32*seg, 32*seg+32)
    const int tseg = seg * 32;

    {
        float A = 1.f, Bv = 0.f;
        #pragma unroll 4
        for (int t = 0; t < 32; t++) {
            float a = sa[(tseg + t) * CST + col], b = sbv[(tseg + t) * CST + col];
            Bv = fmaf(a, Bv, b);
            A *= a;
        }
        segA[seg * 64 + col] = A;
        segB[seg * 64 + col] = Bv;
    }
    __syncthreads();

    // ---------- combine + publish chunk aggregate (seg 0 threads) ----------
    if (seg == 0) {
        float Ac = segA[col], Bc = segB[col];
        #pragma unroll
        for (int s = 1; s < 4; s++) {
            float As_ = segA[s * 64 + col], Bs_ = segB[s * 64 + col];
            Bc = fmaf(As_, Bc, Bs_);
            Ac *= As_;
        }
        aggA[(size_t)sidx * 64 + col] = Ac;
        aggB[(size_t)sidx * 64 + col] = Bc;
        __threadfence();
    }
    __syncthreads();
    if (tid == 0) atomicExch(&status[sidx], 1);

    // ---------- decoupled lookback (seg 0 threads) ----------
    if (seg == 0) {
        float Ar = 1.f, Br = 0.f;
        for (int p = chunk - 1; p >= 0; p--) {
            const int pidx = chain * NC_ + p;
            while (*(volatile int*)(status + pidx) == 0) __nanosleep(32);
            __threadfence();
            float Ap = aggA[(size_t)pidx * 64 + col];
            float Bp = aggB[(size_t)pidx * 64 + col];
            Br = fmaf(Ar, Bp, Br);
            Ar *= Ap;
        }
        shst[col] = fmaf(Ar, 0.5f, Br);   // h at chunk start (h0 = 0.5)
    }
    __syncthreads();

    // ---------- parallel apply (all 4 segments) ----------
    {
        float h = shst[col];
        #pragma unroll
        for (int s = 0; s < 4; s++)       // prefix through earlier segments
            if (s < seg) h = fmaf(segA[s * 64 + col], h, segB[s * 64 + col]);
        #pragma unroll 4
        for (int t = 0; t < 32; t++) {
            float a = sa[(tseg + t) * CST + col], b = sbv[(tseg + t) * CST + col];
            h = fmaf(a, h, b);
            sbv[(tseg + t) * CST + col] = h;
        }
    }
    __syncthreads();

    // ---------- output write (coalesced, pairs) ----------
    if (MODE == 0) {
        for (int idx = tid; idx < BM * 32; idx += 256) {
            const int t = idx >> 5, pr = idx & 31;
            float2 v = *(const float2*)&sbv[t * CST + 2 * pr];
            __half2 hv = __floats2half2_rn(v.x, v.y);
            const int hp = permcol16(hbase + 2 * pr);
            *(__half2*)&outH[(size_t)(bm + t) * H_ + hp] = hv;
        }
    } else {
        for (int idx = tid; idx < BM * 32; idx += 256) {
            const int t = idx >> 5, pr = idx & 31;
            float2 v = *(const float2*)&sbv[t * CST + 2 * pr];
            *(float2*)&outF[(size_t)(bm + t) * H_ + hbase + 2 * pr] = v;
        }
    }
}

// ============================================================================
// launch
// ============================================================================
extern "C" void kernel_launch(void* const* d_in, const int* in_sizes, int n_in,
                              void* d_out, int out_size)
{
    const float* x  = (const float*)d_in[0];
    const float* Wz = (const float*)d_in[1];
    const float* bz = (const float*)d_in[2];
    const float* Wh = (const float*)d_in[3];
    const float* bh = (const float*)d_in[4];
    float* out = (float*)d_out;

    __half *Xh, *X2, *Wc;
    int* st;
    float *aA, *aB;
    cudaGetSymbolAddress((void**)&Xh, g_Xh);
    cudaGetSymbolAddress((void**)&X2, g_X2);
    cudaGetSymbolAddress((void**)&Wc, g_Wc);
    cudaGetSymbolAddress((void**)&st, g_status);
    cudaGetSymbolAddress((void**)&aA, g_aggA);
    cudaGetSymbolAddress((void**)&aB, g_aggB);

    cudaFuncSetAttribute(gemm_fused_kernel<0>,
                         cudaFuncAttributeMaxDynamicSharedMemorySize, GEMM_SMEM);
    cudaFuncSetAttribute(gemm_fused_kernel<1>,
                         cudaFuncAttributeMaxDynamicSharedMemorySize, GEMM_SMEM);

    const size_t HD = (size_t)H_ * D_;
    const size_t LSTRIDE = (size_t)NCHAIN_ * NC_;   // per-layer status stride
    dim3 gemm_grid(N2_ / BN, M_ / BM);     // (16, 128)

    zero_status_kernel<<<16, 256>>>(st);
    round_kernel<<<(M_ * (size_t)D_ / 16 + 255) / 256, 256>>>(
        (const float4*)x, (uint4*)Xh, (int)((size_t)M_ * D_ / 16));

    interleave_kernel<<<(HD / 16 + 255) / 256, 256>>>(
        (const float4*)Wz, (const float4*)Wh, (uint4*)Wc);
    gemm_fused_kernel<0><<<gemm_grid, 256, GEMM_SMEM>>>(
        Xh, Wc, bz, bh, st, aA, aB, X2, nullptr);

    interleave_kernel<<<(HD / 16 + 255) / 256, 256>>>(
        (const float4*)(Wz + HD), (const float4*)(Wh + HD), (uint4*)Wc);
    gemm_fused_kernel<1><<<gemm_grid, 256, GEMM_SMEM>>>(
        X2, Wc, bz + H_, bh + H_, st + LSTRIDE, aA + LSTRIDE * 64,
        aB + LSTRIDE * 64, nullptr, out);
}

// round 11
// speedup vs baseline: 1.3787x; 1.1339x over previous
#include <cuda_runtime.h>
#include <cuda_fp16.h>
#include <cstdint>
#include <math.h>

// ---------------- problem constants ----------------
#define B_  8
#define S_  2048
#define D_  1024
#define H_  1024
#define M_  (B_*S_)        // 16384
#define N2_ 2048           // interleaved (k,ph) output width
#define NC_ 16             // chunks per sequence (S_/BM)
#define NCHAIN_ 128        // chains per layer: 16 h-tiles x 8 batches

// ---------------- scratch ----------------
__device__ __half g_Xh [(size_t)M_ * D_];       // fp16 K-permuted layer-0 input
__device__ __half g_X2 [(size_t)M_ * D_];       // fp16 K-permuted layer-1 input
__device__ __half g_Wc [2 * (size_t)N2_ * D_];  // both layers, interleaved+permuted
__device__ int    g_status[2 * NCHAIN_ * NC_];
__device__ float  g_aggA [2 * NCHAIN_ * NC_ * 64];
__device__ float  g_aggB [2 * NCHAIN_ * NC_ * 64];

// ---------------- helpers ----------------
__device__ __forceinline__ uint32_t h2_as_u32(__half2 h) {
    union { __half2 h; uint32_t u; } cvt; cvt.h = h; return cvt.u;
}
__device__ __forceinline__ uint32_t smem_u32(const void* p) {
    uint32_t a;
    asm("{ .reg .u64 t; cvta.to.shared.u64 t, %1; cvt.u32.u64 %0, t; }" : "=r"(a) : "l"(p));
    return a;
}
__device__ __forceinline__ void cpasync16(uint32_t dst, const void* src) {
    asm volatile("cp.async.cg.shared.global [%0], [%1], 16;" :: "r"(dst), "l"(src));
}
#define CP_COMMIT() asm volatile("cp.async.commit_group;" ::: "memory")

__device__ __forceinline__ void mma_fp16(float* c,
    uint32_t a0, uint32_t a1, uint32_t a2, uint32_t a3, uint32_t b0, uint32_t b1)
{
    asm volatile(
        "mma.sync.aligned.m16n8k16.row.col.f32.f16.f16.f32 "
        "{%0,%1,%2,%3}, {%4,%5,%6,%7}, {%8,%9}, {%0,%1,%2,%3};"
        : "+f"(c[0]), "+f"(c[1]), "+f"(c[2]), "+f"(c[3])
        : "r"(a0), "r"(a1), "r"(a2), "r"(a3), "r"(b0), "r"(b1));
}

// one-exp gates: t=e^kv -> a=sigmoid(-kv)=1/(1+t), z=sigmoid(kv)=t/(1+t)
__device__ __forceinline__ void gates2(float kv, float ph, float& a, float& b) {
    float t = __expf(fminf(kv, 80.f));
    float r = __fdividef(1.f, 1.f + t);
    a = r;
    float z = t * r;
    float g = (ph >= 0.f) ? (ph + 0.5f)
                          : __fdividef(1.f, 1.f + __expf(-ph));
    b = z * g;
}

// K-permutation within each 16-group (fragment pairs contiguous)
__device__ __forceinline__ void perm16(const float4 s0, const float4 s1,
                                       const float4 s2, const float4 s3,
                                       uint4& o0, uint4& o1)
{
    o0 = make_uint4(h2_as_u32(__floats2half2_rn(s0.x, s0.y)),
                    h2_as_u32(__floats2half2_rn(s2.x, s2.y)),
                    h2_as_u32(__floats2half2_rn(s0.z, s0.w)),
                    h2_as_u32(__floats2half2_rn(s2.z, s2.w)));
    o1 = make_uint4(h2_as_u32(__floats2half2_rn(s1.x, s1.y)),
                    h2_as_u32(__floats2half2_rn(s3.x, s3.y)),
                    h2_as_u32(__floats2half2_rn(s1.z, s1.w)),
                    h2_as_u32(__floats2half2_rn(s3.z, s3.w)));
}
__device__ __forceinline__ int permcol16(int h) {
    int j = h & 15, q = j >> 1, r = j & 1;
    int slot = (q < 4) ? (2 * q) : (2 * (q - 4) + 1);
    return (h & ~15) | (slot * 2 + r);
}

// ---------------- fp32 -> fp16 + K-permute (also zeroes lookback status) ----
__global__ __launch_bounds__(256) void round_kernel(
    const float4* __restrict__ src, uint4* __restrict__ dst, int n16,
    int* __restrict__ st)
{
    int i = blockIdx.x * 256 + threadIdx.x;
    if (i < 2 * NCHAIN_ * NC_) st[i] = 0;
    if (i >= n16) return;
    uint4 o0, o1;
    perm16(src[4*i], src[4*i+1], src[4*i+2], src[4*i+3], o0, o1);
    dst[2*i] = o0; dst[2*i+1] = o1;
}

// both layers in one launch: Wc[l][2h] = perm(Wz_l[h]), Wc[l][2h+1] = perm(Wh_l[h])
__global__ __launch_bounds__(256) void interleave_kernel(
    const float4* __restrict__ Wz, const float4* __restrict__ Wh, uint4* __restrict__ Wc)
{
    int i = blockIdx.x * 256 + threadIdx.x;      // over 2*H_*D_/16 = 131072 groups
    int l = i >> 16;                             // layer
    int j = i & 65535;
    int h = j >> 6, s = j & 63;
    const float4* wz = Wz + (size_t)l * (H_ * D_ / 4);
    const float4* wh = Wh + (size_t)l * (H_ * D_ / 4);
    uint4 z0, z1, h0, h1;
    perm16(wz[4*j], wz[4*j+1], wz[4*j+2], wz[4*j+3], z0, z1);
    perm16(wh[4*j], wh[4*j+1], wh[4*j+2], wh[4*j+3], h0, h1);
    uint4* base = Wc + (size_t)l * (N2_ * D_ / 8);
    uint4* rz = base + (size_t)(2*h)   * 128 + 2*s;
    uint4* rh = base + (size_t)(2*h+1) * 128 + 2*s;
    rz[0] = z0; rz[1] = z1;
    rh[0] = h0; rh[1] = h1;
}

// ============================================================================
// Fused fp16 GEMM + gates + chunk scan (decoupled lookback) + direct output
// tile 128x128 (64 h cols), warptile 64x32, BK=32, 4-stage, 2 blocks/SM
// ============================================================================
#define BM 128
#define BN 128
#define BK 32
#define ST 48                            // halfs per smem row (conflict-free)
#define B_OFF (BM * ST)
#define STG_HALFS ((BM + BN) * ST)       // 12288
#define STG_BYTES (STG_HALFS * 2)        // 24576
#define NSTAGE 4
#define GEMM_SMEM (NSTAGE * STG_BYTES)   // 98304
#define GST 136                          // gate tile row stride (floats); 68 words8 = 4 mod 16

__device__ __forceinline__ void load_stage(
    uint32_t sb, const __half* __restrict__ Ag, const __half* __restrict__ Bg,
    int k0, int tid)
{
    #pragma unroll
    for (int i = 0; i < 2; i++) {
        int s = tid + i * 256;
        int r = s >> 2, c = (s & 3) << 3;
        cpasync16(sb + (uint32_t)(r * ST + c) * 2, Ag + (size_t)r * D_ + k0 + c);
    }
    #pragma unroll
    for (int i = 0; i < 2; i++) {
        int s = tid + i * 256;
        int r = s >> 2, c = (s & 3) << 3;
        cpasync16(sb + (uint32_t)(B_OFF + r * ST + c) * 2, Bg + (size_t)r * D_ + k0 + c);
    }
    CP_COMMIT();
}

template<int MODE>   // 0: fp16 K-permuted out (next layer); 1: fp32 out
__global__ __launch_bounds__(256, 2) void gemm_fused_kernel(
    const __half* __restrict__ X, const __half* __restrict__ Wc,
    const float* __restrict__ bz, const float* __restrict__ bh,
    int* __restrict__ status, float* __restrict__ aggA, float* __restrict__ aggB,
    __half* __restrict__ outH, float* __restrict__ outF)
{
    extern __shared__ __align__(16) char smraw[];
    __half* sm = (__half*)smraw;
    const uint32_t sb = smem_u32(sm);
    const int tid = threadIdx.x;
    const int lane = tid & 31, wid = tid >> 5;
    const int g = lane >> 2, tg = lane & 3;
    const int wm = (wid >> 2) * 64;      // 0 / 64
    const int wn = (wid & 3) * 32;       // 0 / 32 / 64 / 96
    const int bm = blockIdx.y * BM;
    const int bn = blockIdx.x * BN;

    const __half* Ag = X  + (size_t)bm * D_;
    const __half* Bg = Wc + (size_t)bn * D_;

    float c[4][4][4];
    #pragma unroll
    for (int mt = 0; mt < 4; mt++)
        #pragma unroll
        for (int nt = 0; nt < 4; nt++)
            #pragma unroll
            for (int r = 0; r < 4; r++) c[mt][nt][r] = 0.f;

    load_stage(sb,                 Ag, Bg, 0,      tid);
    load_stage(sb + STG_BYTES,     Ag, Bg, BK,     tid);
    load_stage(sb + 2 * STG_BYTES, Ag, Bg, 2 * BK, tid);

    const int NK = D_ / BK;   // 32
    for (int kt = 0; kt < NK; kt++) {
        asm volatile("cp.async.wait_group 2;" ::: "memory");
        __syncthreads();
        if (kt + 3 < NK)
            load_stage(sb + (uint32_t)((kt + 3) & 3) * STG_BYTES,
                       Ag, Bg, (kt + 3) * BK, tid);
        else
            CP_COMMIT();

        const __half* As = sm + (kt & 3) * STG_HALFS;
        const __half* Bs = As + B_OFF;

        #pragma unroll
        for (int ks = 0; ks < 2; ks++) {
            const int kb = ks * 16 + 4 * tg;
            uint2 alo[4], ahi[4], bf[4];
            #pragma unroll
            for (int mt = 0; mt < 4; mt++) {
                const int m = wm + mt * 16 + g;
                alo[mt] = *(const uint2*)&As[m * ST + kb];
                ahi[mt] = *(const uint2*)&As[(m + 8) * ST + kb];
            }
            #pragma unroll
            for (int nt = 0; nt < 4; nt++) {
                const int n = wn + nt * 8 + g;
                bf[nt] = *(const uint2*)&Bs[n * ST + kb];
            }
            #pragma unroll
            for (int mt = 0; mt < 4; mt++)
                #pragma unroll
                for (int nt = 0; nt < 4; nt++)
                    mma_fp16(c[mt][nt], alo[mt].x, ahi[mt].x, alo[mt].y, ahi[mt].y,
                             bf[nt].x, bf[nt].y);
        }
    }

    // ---------- epilogue: gates -> interleaved smem tile sg[t][2h|2h+1] ----------
    __syncthreads();
    float* sg   = (float*)smraw;          // [128][GST], (a,b) pairs at 2*col
    float* segA = sg + BM * GST;          // [4][64]
    float* segB = segA + 256;
    float* shst = segB + 256;             // [64]

    const int hbase = bn >> 1;
    #pragma unroll
    for (int nt = 0; nt < 4; nt++) {
        const int hl = (wn >> 1) + nt * 4 + tg;     // 0..63
        const float bzv = bz[hbase + hl], bhv = bh[hbase + hl];
        #pragma unroll
        for (int mt = 0; mt < 4; mt++) {
            const int t0 = wm + mt * 16 + g;
            float a0, b0, a1, b1;
            gates2(c[mt][nt][0] + bzv, c[mt][nt][1] + bhv, a0, b0);
            gates2(c[mt][nt][2] + bzv, c[mt][nt][3] + bhv, a1, b1);
            *(float2*)&sg[t0 * GST + 2 * hl]       = make_float2(a0, b0);
            *(float2*)&sg[(t0 + 8) * GST + 2 * hl] = make_float2(a1, b1);
        }
    }
    __syncthreads();

    // ---------- segment compose: 4 threads/column, 32 steps each ----------
    const int batch = blockIdx.y >> 4;
    const int chunk = blockIdx.y & 15;
    const int chain = blockIdx.x * B_ + batch;
    const int sidx  = chain * NC_ + chunk;

    const int col = tid & 63;
    const int seg = tid >> 6;
    const int tseg = seg * 32;

    {
        float A = 1.f, Bv = 0.f;
        #pragma unroll 4
        for (int t = 0; t < 32; t++) {
            float2 v = *(const float2*)&sg[(tseg + t) * GST + 2 * col];
            Bv = fmaf(v.x, Bv, v.y);
            A *= v.x;
        }
        segA[seg * 64 + col] = A;
        segB[seg * 64 + col] = Bv;
    }
    __syncthreads();

    // ---------- combine + publish chunk aggregate (seg 0 threads) ----------
    if (seg == 0) {
        float Ac = segA[col], Bc = segB[col];
        #pragma unroll
        for (int s = 1; s < 4; s++) {
            float As_ = segA[s * 64 + col], Bs_ = segB[s * 64 + col];
            Bc = fmaf(As_, Bc, Bs_);
            Ac *= As_;
        }
        aggA[(size_t)sidx * 64 + col] = Ac;
        aggB[(size_t)sidx * 64 + col] = Bc;
        __threadfence();
    }
    __syncthreads();
    if (tid == 0) atomicExch(&status[sidx], 1);

    // ---------- decoupled lookback (seg 0 threads) ----------
    if (seg == 0) {
        float Ar = 1.f, Br = 0.f;
        for (int p = chunk - 1; p >= 0; p--) {
            const int pidx = chain * NC_ + p;
            while (*(volatile int*)(status + pidx) == 0) __nanosleep(32);
            __threadfence();
            float Ap = aggA[(size_t)pidx * 64 + col];
            float Bp = aggB[(size_t)pidx * 64 + col];
            Br = fmaf(Ar, Bp, Br);
            Ar *= Ap;
        }
        shst[col] = fmaf(Ar, 0.5f, Br);   // h at chunk start (h0 = 0.5)
    }
    __syncthreads();

    // ---------- parallel apply + direct global store ----------
    {
        float h = shst[col];
        #pragma unroll
        for (int s = 0; s < 4; s++)
            if (s < seg) h = fmaf(segA[s * 64 + col], h, segB[s * 64 + col]);

        if (MODE == 0) {
            const int hp = permcol16(hbase + col);
            __half* po = outH + (size_t)(bm + tseg) * H_ + hp;
            #pragma unroll 4
            for (int t = 0; t < 32; t++) {
                float2 v = *(const float2*)&sg[(tseg + t) * GST + 2 * col];
                h = fmaf(v.x, h, v.y);
                po[(size_t)t * H_] = __float2half_rn(h);
            }
        } else {
            float* po = outF + (size_t)(bm + tseg) * H_ + hbase + col;
            #pragma unroll 4
            for (int t = 0; t < 32; t++) {
                float2 v = *(const float2*)&sg[(tseg + t) * GST + 2 * col];
                h = fmaf(v.x, h, v.y);
                po[(size_t)t * H_] = h;
            }
        }
    }
}

// ============================================================================
// launch
// ============================================================================
extern "C" void kernel_launch(void* const* d_in, const int* in_sizes, int n_in,
                              void* d_out, int out_size)
{
    const float* x  = (const float*)d_in[0];
    const float* Wz = (const float*)d_in[1];
    const float* bz = (const float*)d_in[2];
    const float* Wh = (const float*)d_in[3];
    const float* bh = (const float*)d_in[4];
    float* out = (float*)d_out;

    __half *Xh, *X2, *Wc;
    int* st;
    float *aA, *aB;
    cudaGetSymbolAddress((void**)&Xh, g_Xh);
    cudaGetSymbolAddress((void**)&X2, g_X2);
    cudaGetSymbolAddress((void**)&Wc, g_Wc);
    cudaGetSymbolAddress((void**)&st, g_status);
    cudaGetSymbolAddress((void**)&aA, g_aggA);
    cudaGetSymbolAddress((void**)&aB, g_aggB);

    cudaFuncSetAttribute(gemm_fused_kernel<0>,
                         cudaFuncAttributeMaxDynamicSharedMemorySize, GEMM_SMEM);
    cudaFuncSetAttribute(gemm_fused_kernel<1>,
                         cudaFuncAttributeMaxDynamicSharedMemorySize, GEMM_SMEM);

    const size_t LSTRIDE = (size_t)NCHAIN_ * NC_;
    const size_t WL = (size_t)N2_ * D_;            // halfs per layer of Wc
    dim3 gemm_grid(N2_ / BN, M_ / BM);             // (16, 128)

    round_kernel<<<4096, 256>>>((const float4*)x, (uint4*)Xh,
                                (int)((size_t)M_ * D_ / 16), st);
    interleave_kernel<<<512, 256>>>((const float4*)Wz, (const float4*)Wh, (uint4*)Wc);

    gemm_fused_kernel<0><<<gemm_grid, 256, GEMM_SMEM>>>(
        Xh, Wc, bz, bh, st, aA, aB, X2, nullptr);

    gemm_fused_kernel<1><<<gemm_grid, 256, GEMM_SMEM>>>(
        X2, Wc + WL, bz + H_, bh + H_, st + LSTRIDE, aA + LSTRIDE * 64,
        aB + LSTRIDE * 64, nullptr, out);
}